// round 6
// baseline (speedup 1.0000x reference)
#include <cuda_runtime.h>
#include <cstdint>

// BKT 2-state HMM forward-backward, 128-way time-segmented matrix scan.
// corr: (B,T) int32 ; dynamics_logits: (B,3) f32 ; obs_logits: (B,T,2) f32
// out: (3,B,T,2) f32 = [output_logprobs, state_posteriors, smoothed]

#define BN   8192
#define TT   1024
#define SEG  128
#define L    8
#define LN2F 0.69314718055994531f

__device__ float4 g_P4[SEG * BN];   // raw (unnormalized) segment 2x2 products
__device__ float4 g_ab[SEG * BN];   // (a0,a1,C,-) normalized alpha at segment start
__device__ float2 g_bb[SEG * BN];   // (b0,b1) beta at segment end

__device__ __forceinline__ void trans_from_dyn(const float* __restrict__ dyn, int row,
                                               float& t00, float& t10, float& t01, float& t11)
{
    float d0 = dyn[row * 3 + 0];
    float d1 = dyn[row * 3 + 1];
    float e0 = __expf(d0), e1 = __expf(d1);
    float r0 = __frcp_rn(1.f + e0);
    float r1 = __frcp_rn(1.f + e1);
    t00 = r0;      t10 = e0 * r0;   // src=0 column (sums to 1)
    t01 = e1 * r1; t11 = r1;        // src=1 column (sums to 1)
}

// ---------------- K1: per-segment 2x2 matrix products (smem-staged loads) ----------------
__global__ __launch_bounds__(256)
void k1_products(const int* __restrict__ corr,
                 const float* __restrict__ dyn,
                 const float* __restrict__ obs)
{
    __shared__ float sO[256 * 17];
    __shared__ int   sC[256 * 9];

    const int tid  = threadIdx.x;
    const int row0 = (blockIdx.x & 31) * 256;   // 32 blocks per segment
    const int seg  = blockIdx.x >> 5;
    const int row  = row0 + tid;

    // coalesced load: obs 256 rows x 16 floats
#pragma unroll
    for (int i = 0; i < 4; i++) {
        int idx = i * 256 + tid;
        int r = idx >> 2, c = idx & 3;
        float4 v = *(const float4*)(obs + (size_t)(row0 + r) * (TT * 2) + seg * (2 * L) + c * 4);
        sO[r * 17 + c * 4 + 0] = v.x;
        sO[r * 17 + c * 4 + 1] = v.y;
        sO[r * 17 + c * 4 + 2] = v.z;
        sO[r * 17 + c * 4 + 3] = v.w;
    }
    // coalesced load: corr 256 rows x 8 ints
#pragma unroll
    for (int i = 0; i < 2; i++) {
        int idx = i * 256 + tid;
        int r = idx >> 1, h = idx & 1;
        int4 v = *(const int4*)(corr + (size_t)(row0 + r) * TT + seg * L + h * 4);
        sC[r * 9 + h * 4 + 0] = v.x;
        sC[r * 9 + h * 4 + 1] = v.y;
        sC[r * 9 + h * 4 + 2] = v.z;
        sC[r * 9 + h * 4 + 3] = v.w;
    }
    __syncthreads();

    float t00, t10, t01, t11;
    trans_from_dyn(dyn, row, t00, t10, t01, t11);

    float A00 = 1.f, A01 = 0.f, A10 = 0.f, A11 = 1.f;
#pragma unroll
    for (int j = 0; j < L; j++) {
        float o0 = sO[tid * 17 + 2 * j];
        float o1 = sO[tid * 17 + 2 * j + 1];
        int   y  = sC[tid * 9 + j];
        float e0 = __expf(o0), e1 = __expf(o1);
        float r0 = __frcp_rn(1.f + e0);
        float r1 = __frcp_rn(1.f + e1);
        float py0 = y ? e0 * r0 : r0;
        float py1 = y ? r1 : e1 * r1;

        float m00 = t00 * py0, m01 = t01 * py1;
        float m10 = t10 * py0, m11 = t11 * py1;
        float n00 = m00 * A00 + m01 * A10;
        float n01 = m00 * A01 + m01 * A11;
        float n10 = m10 * A00 + m11 * A10;
        float n11 = m10 * A01 + m11 * A11;
        A00 = n00; A01 = n01; A10 = n10; A11 = n11;
    }
    // raw product: entries in [~1e-24, 1] — no underflow possible, K2 rescales
    g_P4[seg * BN + row] = make_float4(A00, A01, A10, A11);
}

// ---------------- K2: boundary scan over segments (alpha & beta interleaved) ----------------
__global__ __launch_bounds__(256)
void k2_scan(const float* __restrict__ dyn)
{
    const int row = blockIdx.x * 256 + threadIdx.x;

    float d2 = dyn[row * 3 + 2];
    float ed2 = __expf(d2);
    float ri2 = __frcp_rn(1.f + ed2);
    float a0 = ri2, a1 = ed2 * ri2;
    int Ea = 0;
    float b0 = 1.f, b1 = 1.f;

#pragma unroll 4
    for (int k = 0; k < SEG; k++) {
        // ---- alpha chain (ascending) ----
        int gi = k * BN + row;
        float s  = a0 + a1;
        float rs = __frcp_rn(s);
        float C  = (float)Ea * LN2F + __logf(s);
        g_ab[gi] = make_float4(a0 * rs, a1 * rs, C, 0.f);

        float4 P = g_P4[gi];
        float na0 = P.x * a0 + P.y * a1;
        float na1 = P.z * a0 + P.w * a1;
        float ss = na0 + na1;
        int eb = (__float_as_int(ss) >> 23) & 0xFF;
        float sca = __int_as_float((254 - eb) << 23);
        a0 = na0 * sca; a1 = na1 * sca;
        Ea += eb - 127;

        // ---- beta chain (descending, independent) ----
        int kb  = SEG - 1 - k;
        int gib = kb * BN + row;
        g_bb[gib] = make_float2(b0, b1);
        if (kb > 0) {
            float4 Pb = g_P4[gib];
            float nb0 = Pb.x * b0 + Pb.z * b1;   // P^T * b
            float nb1 = Pb.y * b0 + Pb.w * b1;
            float sb = nb0 + nb1;
            int ebb = (__float_as_int(sb) >> 23) & 0xFF;
            float scb = __int_as_float((254 - ebb) << 23);
            b0 = nb0 * scb; b1 = nb1 * scb;
        }
    }
}

// ---------------- K3: per-segment outputs (bwd-first, fused fwd) ----------------
__global__ __launch_bounds__(128, 5)
void k3_outputs(const int* __restrict__ corr,
                const float* __restrict__ dyn,
                const float* __restrict__ obs,
                float* __restrict__ out)
{
    __shared__ float sP[128 * 17];   // staging: obs in, then pred out
    __shared__ float sQ[128 * 17];   // staging: corr in, then post out
    __shared__ float sS[128 * 17];   // smoothed out

    const int tid  = threadIdx.x;
    const int row0 = blockIdx.x * 128;
    const int row  = row0 + tid;
    const int seg  = blockIdx.y;

    // coalesced stage: obs 128 rows x 16 floats
#pragma unroll
    for (int i = 0; i < 4; i++) {
        int idx = i * 128 + tid;
        int r = idx >> 2, c = idx & 3;
        float4 v = *(const float4*)(obs + (size_t)(row0 + r) * (TT * 2) + seg * (2 * L) + c * 4);
        sP[r * 17 + c * 4 + 0] = v.x;
        sP[r * 17 + c * 4 + 1] = v.y;
        sP[r * 17 + c * 4 + 2] = v.z;
        sP[r * 17 + c * 4 + 3] = v.w;
    }
    // coalesced stage: corr 128 rows x 8 ints (as float bits)
#pragma unroll
    for (int i = 0; i < 2; i++) {
        int idx = i * 128 + tid;
        int r = idx >> 1, h = idx & 1;
        int4 v = *(const int4*)(corr + (size_t)(row0 + r) * TT + seg * L + h * 4);
        sQ[r * 17 + h * 4 + 0] = __int_as_float(v.x);
        sQ[r * 17 + h * 4 + 1] = __int_as_float(v.y);
        sQ[r * 17 + h * 4 + 2] = __int_as_float(v.z);
        sQ[r * 17 + h * 4 + 3] = __int_as_float(v.w);
    }
    __syncthreads();

    // pull own row to registers (staging slots become output slots afterwards)
    float o[2 * L];
#pragma unroll
    for (int k = 0; k < 2 * L; k++) o[k] = sP[tid * 17 + k];
    unsigned ymask = 0;
#pragma unroll
    for (int j = 0; j < L; j++)
        ymask |= ((unsigned)__float_as_int(sQ[tid * 17 + j]) & 1u) << j;

    float t00, t10, t01, t11;
    trans_from_dyn(dyn, row, t00, t10, t01, t11);

    const int gi = seg * BN + row;
    float4 ab = g_ab[gi];
    float2 bb = g_bb[gi];
    float a0 = ab.x, a1 = ab.y, C = ab.z;
    float b0 = bb.x, b1 = bb.y;

    // ---- backward sub-walk: record beta_t, replace obs logits with emissions ----
    float b0s[L], b1s[L];
#pragma unroll
    for (int j = L - 1; j >= 0; j--) {
        int y = (ymask >> j) & 1;
        float e0 = __expf(o[2 * j]), e1 = __expf(o[2 * j + 1]);
        float r0 = __frcp_rn(1.f + e0);
        float r1 = __frcp_rn(1.f + e1);
        float py0 = y ? e0 * r0 : r0;
        float py1 = y ? r1 : e1 * r1;
        o[2 * j]     = py0;
        o[2 * j + 1] = py1;
        b0s[j] = b0; b1s[j] = b1;
        // beta update to t-1 (no in-segment rescale needed: >= ~1e-24)
        float u0 = py0 * b0;
        float u1 = py1 * b1;
        b0 = t00 * u0 + t10 * u1;
        b1 = t01 * u0 + t11 * u1;
    }

    // ---- forward sub-walk: pred + post + smoothed ----
#pragma unroll
    for (int j = 0; j < L; j++) {
        int y = (ymask >> j) & 1;
        float py0 = o[2 * j];
        float py1 = o[2 * j + 1];

        float jj0 = a0 * py0;
        float jj1 = a1 * py1;
        float js  = jj0 + jj1;               // predictive prob of observed symbol
        float ljs = __logf(js);
        float lns = __logf(1.f - js);        // predictive probs sum to 1 (a normalized)
        float post0 = __logf(jj0) + C;
        float post1 = __logf(jj1) + C;

        float f  = jj0 * __frcp_rn(js);
        float fc = 1.f - f;

        // smoothed: normalize(f .* beta_t)
        float g0 = f  * b0s[j];
        float g1 = fc * b1s[j];
        float rg = __frcp_rn(g0 + g1);

        sP[tid * 17 + 2 * j]     = y ? lns : ljs;
        sP[tid * 17 + 2 * j + 1] = y ? ljs : lns;
        sQ[tid * 17 + 2 * j]     = post0;
        sQ[tid * 17 + 2 * j + 1] = post1;
        sS[tid * 17 + 2 * j]     = __logf(g0 * rg);
        sS[tid * 17 + 2 * j + 1] = __logf(g1 * rg);

        a0 = t00 * f + t01 * fc;             // stays normalized (T columns sum to 1)
        a1 = t10 * f + t11 * fc;
        C += ljs;
    }
    __syncthreads();

    float* outPred = out;
    float* outPost = out + (size_t)BN * TT * 2;
    float* outSm   = out + (size_t)2 * BN * TT * 2;
#pragma unroll
    for (int i = 0; i < 16; i++) {
        int idx = i * 128 + tid;
        int r = idx >> 4, p = idx & 15;
        size_t g = (size_t)(row0 + r) * (TT * 2) + (size_t)seg * (L * 2) + p;
        outPred[g] = sP[r * 17 + p];
        outPost[g] = sQ[r * 17 + p];
        outSm[g]   = sS[r * 17 + p];
    }
}

extern "C" void kernel_launch(void* const* d_in, const int* in_sizes, int n_in,
                              void* d_out, int out_size)
{
    const int*   corr = (const int*)d_in[0];
    const float* dyn  = (const float*)d_in[1];
    const float* obs  = (const float*)d_in[2];
    float* out = (float*)d_out;

    k1_products<<<SEG * (BN / 256), 256>>>(corr, dyn, obs);
    k2_scan<<<BN / 256, 256>>>(dyn);
    dim3 g3(BN / 128, SEG);
    k3_outputs<<<g3, 128>>>(corr, dyn, obs, out);
}

// round 7
// speedup vs baseline: 1.0768x; 1.0768x over previous
#include <cuda_runtime.h>
#include <cstdint>

// BKT 2-state HMM forward-backward, 128-way time-segmented matrix scan.
// corr: (B,T) int32 ; dynamics_logits: (B,3) f32 ; obs_logits: (B,T,2) f32
// out: (3,B,T,2) f32 = [output_logprobs, state_posteriors, smoothed]
// Thread mapping: threads = consecutive segments of ONE row -> every warp
// touches a contiguous 2KB span of obs/corr/out (full DRAM efficiency).

#define BN   8192
#define TT   1024
#define SEG  128
#define L    8
#define LN2F 0.69314718055994531f

__device__ float4 g_P4[SEG * BN];   // row-major [row*SEG+seg]: raw segment 2x2 products
__device__ float4 g_ab[SEG * BN];   // seg-major [seg*BN+row]: (a0,a1,C,-) at segment start
__device__ float2 g_bb[SEG * BN];   // seg-major [seg*BN+row]: (b0,b1) at segment end

__device__ __forceinline__ void trans_from_dyn(const float* __restrict__ dyn, int row,
                                               float& t00, float& t10, float& t01, float& t11)
{
    float d0 = dyn[row * 3 + 0];
    float d1 = dyn[row * 3 + 1];
    float e0 = __expf(d0), e1 = __expf(d1);
    float r0 = __frcp_rn(1.f + e0);
    float r1 = __frcp_rn(1.f + e1);
    t00 = r0;      t10 = e0 * r0;   // src=0 column (sums to 1)
    t01 = e1 * r1; t11 = r1;        // src=1 column (sums to 1)
}

// ---------------- K1: per-segment 2x2 matrix products (contiguous per block) ----------------
__global__ __launch_bounds__(256)
void k1_products(const int* __restrict__ corr,
                 const float* __restrict__ dyn,
                 const float* __restrict__ obs)
{
    const int tid = threadIdx.x;
    const int row = blockIdx.x * 2 + (tid >> 7);   // 2 rows per block
    const int seg = tid & 127;

    // own 64B obs chunk + 32B corr chunk (warp covers contiguous 2KB / 1KB)
    float o[2 * L];
    const float4* op = (const float4*)(obs + (size_t)row * (TT * 2) + seg * (2 * L));
#pragma unroll
    for (int i = 0; i < 4; i++) {
        float4 v = op[i];
        o[4 * i + 0] = v.x; o[4 * i + 1] = v.y;
        o[4 * i + 2] = v.z; o[4 * i + 3] = v.w;
    }
    int yb[L];
    const int4* cp = (const int4*)(corr + (size_t)row * TT + seg * L);
#pragma unroll
    for (int i = 0; i < 2; i++) {
        int4 v = cp[i];
        yb[4 * i + 0] = v.x; yb[4 * i + 1] = v.y;
        yb[4 * i + 2] = v.z; yb[4 * i + 3] = v.w;
    }

    float t00, t10, t01, t11;
    trans_from_dyn(dyn, row, t00, t10, t01, t11);

    float A00 = 1.f, A01 = 0.f, A10 = 0.f, A11 = 1.f;
#pragma unroll
    for (int j = 0; j < L; j++) {
        float e0 = __expf(o[2 * j]), e1 = __expf(o[2 * j + 1]);
        float r0 = __frcp_rn(1.f + e0);
        float r1 = __frcp_rn(1.f + e1);
        float py0 = yb[j] ? e0 * r0 : r0;
        float py1 = yb[j] ? r1 : e1 * r1;

        float m00 = t00 * py0, m01 = t01 * py1;
        float m10 = t10 * py0, m11 = t11 * py1;
        float n00 = m00 * A00 + m01 * A10;
        float n01 = m00 * A01 + m01 * A11;
        float n10 = m10 * A00 + m11 * A10;
        float n11 = m10 * A01 + m11 * A11;
        A00 = n00; A01 = n01; A10 = n10; A11 = n11;
    }
    // raw product (>= ~1e-24, no underflow); K2 rescales
    g_P4[row * SEG + seg] = make_float4(A00, A01, A10, A11);   // coalesced contiguous
}

// ---------------- K2: boundary scan over segments (alpha & beta interleaved) ----------------
__global__ __launch_bounds__(256)
void k2_scan(const float* __restrict__ dyn)
{
    const int row = blockIdx.x * 256 + threadIdx.x;

    float d2 = dyn[row * 3 + 2];
    float ed2 = __expf(d2);
    float ri2 = __frcp_rn(1.f + ed2);
    float a0 = ri2, a1 = ed2 * ri2;
    int Ea = 0;
    float b0 = 1.f, b1 = 1.f;

#pragma unroll 8
    for (int k = 0; k < SEG; k++) {
        // ---- alpha chain (ascending); P4 row-major: 8 iters share one 128B line in L1 ----
        float s  = a0 + a1;
        float rs = __frcp_rn(s);
        float C  = (float)Ea * LN2F + __logf(s);
        g_ab[k * BN + row] = make_float4(a0 * rs, a1 * rs, C, 0.f);   // coalesced

        float4 P = g_P4[row * SEG + k];
        float na0 = P.x * a0 + P.y * a1;
        float na1 = P.z * a0 + P.w * a1;
        float ss = na0 + na1;
        int eb = (__float_as_int(ss) >> 23) & 0xFF;
        float sca = __int_as_float((254 - eb) << 23);
        a0 = na0 * sca; a1 = na1 * sca;
        Ea += eb - 127;

        // ---- beta chain (descending, independent) ----
        int kb = SEG - 1 - k;
        g_bb[kb * BN + row] = make_float2(b0, b1);                    // coalesced
        if (kb > 0) {
            float4 Pb = g_P4[row * SEG + kb];
            float nb0 = Pb.x * b0 + Pb.z * b1;   // P^T * b
            float nb1 = Pb.y * b0 + Pb.w * b1;
            float sb = nb0 + nb1;
            int ebb = (__float_as_int(sb) >> 23) & 0xFF;
            float scb = __int_as_float((254 - ebb) << 23);
            b0 = nb0 * scb; b1 = nb1 * scb;
        }
    }
}

// ---------------- K3: per-segment outputs (bwd-first, fused fwd; no smem) ----------------
__global__ __launch_bounds__(128, 6)
void k3_outputs(const int* __restrict__ corr,
                const float* __restrict__ dyn,
                const float* __restrict__ obs,
                float* __restrict__ out)
{
    const int row = blockIdx.x;
    const int seg = threadIdx.x;

    // direct contiguous-per-warp loads (same pattern as K1)
    float o[2 * L];
    const float4* op = (const float4*)(obs + (size_t)row * (TT * 2) + seg * (2 * L));
#pragma unroll
    for (int i = 0; i < 4; i++) {
        float4 v = op[i];
        o[4 * i + 0] = v.x; o[4 * i + 1] = v.y;
        o[4 * i + 2] = v.z; o[4 * i + 3] = v.w;
    }
    unsigned ymask = 0;
    const int4* cp = (const int4*)(corr + (size_t)row * TT + seg * L);
#pragma unroll
    for (int i = 0; i < 2; i++) {
        int4 v = cp[i];
        ymask |= (unsigned)(v.x & 1) << (4 * i + 0);
        ymask |= (unsigned)(v.y & 1) << (4 * i + 1);
        ymask |= (unsigned)(v.z & 1) << (4 * i + 2);
        ymask |= (unsigned)(v.w & 1) << (4 * i + 3);
    }

    float t00, t10, t01, t11;
    trans_from_dyn(dyn, row, t00, t10, t01, t11);

    const int gi = seg * BN + row;        // L2-hot (written by K2 just before)
    float4 ab = g_ab[gi];
    float2 bb = g_bb[gi];
    float a0 = ab.x, a1 = ab.y, C = ab.z;
    float b0 = bb.x, b1 = bb.y;

    // ---- backward sub-walk: record beta_t, replace obs logits with emissions ----
    float b0s[L], b1s[L];
#pragma unroll
    for (int j = L - 1; j >= 0; j--) {
        int y = (ymask >> j) & 1;
        float e0 = __expf(o[2 * j]), e1 = __expf(o[2 * j + 1]);
        float r0 = __frcp_rn(1.f + e0);
        float r1 = __frcp_rn(1.f + e1);
        float py0 = y ? e0 * r0 : r0;
        float py1 = y ? r1 : e1 * r1;
        o[2 * j]     = py0;
        o[2 * j + 1] = py1;
        b0s[j] = b0; b1s[j] = b1;
        float u0 = py0 * b0;
        float u1 = py1 * b1;
        b0 = t00 * u0 + t10 * u1;   // no in-segment rescale needed (>= ~1e-24)
        b1 = t01 * u0 + t11 * u1;
    }

    // output pointers: thread owns 64B per plane; warp spans contiguous 2KB
    float4* predP = (float4*)(out + (size_t)row * (TT * 2) + seg * (2 * L));
    float4* postP = (float4*)(out + (size_t)BN * TT * 2 + (size_t)row * (TT * 2) + seg * (2 * L));
    float4* smP   = (float4*)(out + (size_t)2 * BN * TT * 2 + (size_t)row * (TT * 2) + seg * (2 * L));

    // ---- forward sub-walk: pred + post + smoothed, float4 stores every 2 steps ----
    float pr0 = 0.f, pr1 = 0.f, po0 = 0.f, po1 = 0.f, sm0p = 0.f, sm1p = 0.f;
#pragma unroll
    for (int j = 0; j < L; j++) {
        int y = (ymask >> j) & 1;
        float py0 = o[2 * j];
        float py1 = o[2 * j + 1];

        float jj0 = a0 * py0;
        float jj1 = a1 * py1;
        float js  = jj0 + jj1;               // predictive prob of observed symbol
        float ljs = __logf(js);
        float lns = __logf(1.f - js);        // predictive probs sum to 1 (a normalized)
        float lp0 = y ? lns : ljs;
        float lp1 = y ? ljs : lns;
        float post0 = __logf(jj0) + C;
        float post1 = __logf(jj1) + C;

        float f  = jj0 * __frcp_rn(js);
        float fc = 1.f - f;

        float g0 = f  * b0s[j];
        float g1 = fc * b1s[j];
        float rg = __frcp_rn(g0 + g1);
        float s0 = __logf(g0 * rg);
        float s1 = __logf(g1 * rg);

        a0 = t00 * f + t01 * fc;             // stays normalized (T columns sum to 1)
        a1 = t10 * f + t11 * fc;
        C += ljs;

        if ((j & 1) == 0) {
            pr0 = lp0; pr1 = lp1; po0 = post0; po1 = post1; sm0p = s0; sm1p = s1;
        } else {
            predP[j >> 1] = make_float4(pr0, pr1, lp0, lp1);
            postP[j >> 1] = make_float4(po0, po1, post0, post1);
            smP[j >> 1]   = make_float4(sm0p, sm1p, s0, s1);
        }
    }
}

extern "C" void kernel_launch(void* const* d_in, const int* in_sizes, int n_in,
                              void* d_out, int out_size)
{
    const int*   corr = (const int*)d_in[0];
    const float* dyn  = (const float*)d_in[1];
    const float* obs  = (const float*)d_in[2];
    float* out = (float*)d_out;

    k1_products<<<BN / 2, 256>>>(corr, dyn, obs);
    k2_scan<<<BN / 256, 256>>>(dyn);
    k3_outputs<<<BN, 128>>>(corr, dyn, obs, out);
}

// round 8
// speedup vs baseline: 1.1639x; 1.0809x over previous
#include <cuda_runtime.h>
#include <cstdint>

// BKT 2-state HMM forward-backward, 128-way time-segmented matrix scan.
// corr: (B,T) int32 ; dynamics_logits: (B,3) f32 ; obs_logits: (B,T,2) f32
// out: (3,B,T,2) f32 = [output_logprobs, state_posteriors, smoothed]
// Thread mapping: threads = consecutive segments of ONE row -> every warp
// touches a contiguous 2KB span of obs/corr/out.

#define BN   8192
#define TT   1024
#define SEG  128
#define L    8
#define LN2F 0.69314718055994531f

__device__ float4 g_P4[SEG * BN];   // row-major [row*SEG+seg]: raw segment 2x2 products
__device__ float4 g_ab[SEG * BN];   // seg-major [seg*BN+row]: (a0,a1,C,-) at segment start
__device__ float2 g_bb[SEG * BN];   // seg-major [seg*BN+row]: (b0,b1) at segment end

__device__ __forceinline__ void trans_from_dyn(const float* __restrict__ dyn, int row,
                                               float& t00, float& t10, float& t01, float& t11)
{
    float d0 = dyn[row * 3 + 0];
    float d1 = dyn[row * 3 + 1];
    float e0 = __expf(d0), e1 = __expf(d1);
    float r0 = __frcp_rn(1.f + e0);
    float r1 = __frcp_rn(1.f + e1);
    t00 = r0;      t10 = e0 * r0;   // src=0 column (sums to 1)
    t01 = e1 * r1; t11 = r1;        // src=1 column (sums to 1)
}

// ---------------- K1: per-segment 2x2 matrix products (contiguous per block) ----------------
__global__ __launch_bounds__(256)
void k1_products(const int* __restrict__ corr,
                 const float* __restrict__ dyn,
                 const float* __restrict__ obs)
{
    const int tid = threadIdx.x;
    const int row = blockIdx.x * 2 + (tid >> 7);   // 2 rows per block
    const int seg = tid & 127;

    float o[2 * L];
    const float4* op = (const float4*)(obs + (size_t)row * (TT * 2) + seg * (2 * L));
#pragma unroll
    for (int i = 0; i < 4; i++) {
        float4 v = op[i];
        o[4 * i + 0] = v.x; o[4 * i + 1] = v.y;
        o[4 * i + 2] = v.z; o[4 * i + 3] = v.w;
    }
    int yb[L];
    const int4* cp = (const int4*)(corr + (size_t)row * TT + seg * L);
#pragma unroll
    for (int i = 0; i < 2; i++) {
        int4 v = cp[i];
        yb[4 * i + 0] = v.x; yb[4 * i + 1] = v.y;
        yb[4 * i + 2] = v.z; yb[4 * i + 3] = v.w;
    }

    float t00, t10, t01, t11;
    trans_from_dyn(dyn, row, t00, t10, t01, t11);

    float A00 = 1.f, A01 = 0.f, A10 = 0.f, A11 = 1.f;
#pragma unroll
    for (int j = 0; j < L; j++) {
        float e0 = __expf(o[2 * j]), e1 = __expf(o[2 * j + 1]);
        float r0 = __frcp_rn(1.f + e0);
        float r1 = __frcp_rn(1.f + e1);
        float py0 = yb[j] ? e0 * r0 : r0;
        float py1 = yb[j] ? r1 : e1 * r1;

        float m00 = t00 * py0, m01 = t01 * py1;
        float m10 = t10 * py0, m11 = t11 * py1;
        float n00 = m00 * A00 + m01 * A10;
        float n01 = m00 * A01 + m01 * A11;
        float n10 = m10 * A00 + m11 * A10;
        float n11 = m10 * A01 + m11 * A11;
        A00 = n00; A01 = n01; A10 = n10; A11 = n11;
    }
    g_P4[row * SEG + seg] = make_float4(A00, A01, A10, A11);   // coalesced contiguous
}

// ---------------- K2: boundary scan over segments (alpha & beta interleaved) ----------------
__global__ __launch_bounds__(256)
void k2_scan(const float* __restrict__ dyn)
{
    const int row = blockIdx.x * 256 + threadIdx.x;

    float d2 = dyn[row * 3 + 2];
    float ed2 = __expf(d2);
    float ri2 = __frcp_rn(1.f + ed2);
    float a0 = ri2, a1 = ed2 * ri2;
    int Ea = 0;
    float b0 = 1.f, b1 = 1.f;

#pragma unroll 8
    for (int k = 0; k < SEG; k++) {
        float s  = a0 + a1;
        float rs = __frcp_rn(s);
        float C  = (float)Ea * LN2F + __logf(s);
        g_ab[k * BN + row] = make_float4(a0 * rs, a1 * rs, C, 0.f);

        float4 P = g_P4[row * SEG + k];
        float na0 = P.x * a0 + P.y * a1;
        float na1 = P.z * a0 + P.w * a1;
        float ss = na0 + na1;
        int eb = (__float_as_int(ss) >> 23) & 0xFF;
        float sca = __int_as_float((254 - eb) << 23);
        a0 = na0 * sca; a1 = na1 * sca;
        Ea += eb - 127;

        int kb = SEG - 1 - k;
        g_bb[kb * BN + row] = make_float2(b0, b1);
        if (kb > 0) {
            float4 Pb = g_P4[row * SEG + kb];
            float nb0 = Pb.x * b0 + Pb.z * b1;   // P^T * b
            float nb1 = Pb.y * b0 + Pb.w * b1;
            float sb = nb0 + nb1;
            int ebb = (__float_as_int(sb) >> 23) & 0xFF;
            float scb = __int_as_float((254 - ebb) << 23);
            b0 = nb0 * scb; b1 = nb1 * scb;
        }
    }
}

// ---------------- K3: per-segment outputs (fwd-first, lean registers, no smem) ----------------
__global__ __launch_bounds__(128, 4)
void k3_outputs(const int* __restrict__ corr,
                const float* __restrict__ dyn,
                const float* __restrict__ obs,
                float* __restrict__ out)
{
    const int row = blockIdx.x;
    const int seg = threadIdx.x;

    float o[2 * L];
    const float4* op = (const float4*)(obs + (size_t)row * (TT * 2) + seg * (2 * L));
#pragma unroll
    for (int i = 0; i < 4; i++) {
        float4 v = op[i];
        o[4 * i + 0] = v.x; o[4 * i + 1] = v.y;
        o[4 * i + 2] = v.z; o[4 * i + 3] = v.w;
    }
    unsigned ymask = 0;
    const int4* cp = (const int4*)(corr + (size_t)row * TT + seg * L);
#pragma unroll
    for (int i = 0; i < 2; i++) {
        int4 v = cp[i];
        ymask |= (unsigned)(v.x & 1) << (4 * i + 0);
        ymask |= (unsigned)(v.y & 1) << (4 * i + 1);
        ymask |= (unsigned)(v.z & 1) << (4 * i + 2);
        ymask |= (unsigned)(v.w & 1) << (4 * i + 3);
    }

    float t00, t10, t01, t11;
    trans_from_dyn(dyn, row, t00, t10, t01, t11);

    const int gi = seg * BN + row;        // L2-hot (written by K2 just before)
    float4 ab = g_ab[gi];
    float a0 = ab.x, a1 = ab.y, C = ab.z;

    float4* predP = (float4*)(out + (size_t)row * (TT * 2) + seg * (2 * L));
    float4* postP = (float4*)(out + (size_t)BN * TT * 2 + (size_t)row * (TT * 2) + seg * (2 * L));
    float4* smP   = (float4*)(out + (size_t)2 * BN * TT * 2 + (size_t)row * (TT * 2) + seg * (2 * L));

    // ---- forward sub-walk: pred + post + f0; o[] replaced in place by emissions ----
    float f0s[L];
    float pr0 = 0.f, pr1 = 0.f, po0 = 0.f, po1 = 0.f;
#pragma unroll
    for (int j = 0; j < L; j++) {
        int y = (ymask >> j) & 1;
        float e0 = __expf(o[2 * j]), e1 = __expf(o[2 * j + 1]);
        float r0 = __frcp_rn(1.f + e0);
        float r1 = __frcp_rn(1.f + e1);
        float py0 = y ? e0 * r0 : r0;
        float py1 = y ? r1 : e1 * r1;
        o[2 * j]     = py0;              // reuse registers: logits -> emissions
        o[2 * j + 1] = py1;

        float jj0 = a0 * py0;
        float jj1 = a1 * py1;
        float js  = jj0 + jj1;           // predictive prob of observed symbol
        float ljs = __logf(js);
        float lns = __logf(1.f - js);    // predictive probs sum to 1 (a normalized)
        float lp0 = y ? lns : ljs;
        float lp1 = y ? ljs : lns;
        float post0 = __logf(jj0) + C;
        float post1 = __logf(jj1) + C;

        float f  = jj0 * __frcp_rn(js);
        f0s[j] = f;
        float fc = 1.f - f;
        a0 = t00 * f + t01 * fc;         // stays normalized (T columns sum to 1)
        a1 = t10 * f + t11 * fc;
        C += ljs;

        if ((j & 1) == 0) {
            pr0 = lp0; pr1 = lp1; po0 = post0; po1 = post1;
        } else {
            predP[j >> 1] = make_float4(pr0, pr1, lp0, lp1);
            postP[j >> 1] = make_float4(po0, po1, post0, post1);
        }
    }

    // ---- backward sub-walk: smoothed (descending; store pairs) ----
    float2 bb = g_bb[gi];
    float b0 = bb.x, b1 = bb.y;
    float sh0 = 0.f, sh1 = 0.f;          // held values for the odd j of each pair
#pragma unroll
    for (int j = L - 1; j >= 0; j--) {
        float f  = f0s[j];
        float fc = 1.f - f;
        float g0 = f  * b0;
        float g1 = fc * b1;
        float rg = __frcp_rn(g0 + g1);
        float s0 = __logf(g0 * rg);
        float s1 = __logf(g1 * rg);

        if (j & 1) {
            sh0 = s0; sh1 = s1;
        } else {
            smP[j >> 1] = make_float4(s0, s1, sh0, sh1);
        }

        // beta update to t-1 (no in-segment rescale needed: >= ~1e-24)
        float u0 = o[2 * j]     * b0;
        float u1 = o[2 * j + 1] * b1;
        b0 = t00 * u0 + t10 * u1;
        b1 = t01 * u0 + t11 * u1;
    }
}

extern "C" void kernel_launch(void* const* d_in, const int* in_sizes, int n_in,
                              void* d_out, int out_size)
{
    const int*   corr = (const int*)d_in[0];
    const float* dyn  = (const float*)d_in[1];
    const float* obs  = (const float*)d_in[2];
    float* out = (float*)d_out;

    k1_products<<<BN / 2, 256>>>(corr, dyn, obs);
    k2_scan<<<BN / 256, 256>>>(dyn);
    k3_outputs<<<BN, 128>>>(corr, dyn, obs, out);
}

// round 9
// speedup vs baseline: 1.3643x; 1.1721x over previous
#include <cuda_runtime.h>
#include <cstdint>

// BKT 2-state HMM forward-backward, 128-way time-segmented matrix scan.
// corr: (B,T) int32 ; dynamics_logits: (B,3) f32 ; obs_logits: (B,T,2) f32
// out: (3,B,T,2) f32 = [output_logprobs, state_posteriors, smoothed]

#define BN   8192
#define TT   1024
#define SEG  128
#define L    8
#define LN2F 0.69314718055994531f

__device__ float4 g_P4[SEG * BN];   // row-major [row*SEG+seg]: raw segment 2x2 products
__device__ float4 g_ab[SEG * BN];   // seg-major [seg*BN+row]: (a0,a1,C,-) at segment start
__device__ float2 g_bb[SEG * BN];   // seg-major [seg*BN+row]: (b0,b1) at segment end

// fast hardware reciprocal (single MUFU.RCP, ~16cyc, rel err ~2^-23)
__device__ __forceinline__ float frcp(float x) {
    float r;
    asm("rcp.approx.f32 %0, %1;" : "=f"(r) : "f"(x));
    return r;
}

__device__ __forceinline__ void trans_from_dyn(const float* __restrict__ dyn, int row,
                                               float& t00, float& t10, float& t01, float& t11)
{
    float d0 = dyn[row * 3 + 0];
    float d1 = dyn[row * 3 + 1];
    float e0 = __expf(d0), e1 = __expf(d1);
    float r0 = frcp(1.f + e0);
    float r1 = frcp(1.f + e1);
    t00 = r0;      t10 = e0 * r0;   // src=0 column (sums to 1)
    t01 = e1 * r1; t11 = r1;        // src=1 column (sums to 1)
}

// ---------------- K1: per-segment 2x2 matrix products (contiguous per block) ----------------
__global__ __launch_bounds__(256)
void k1_products(const int* __restrict__ corr,
                 const float* __restrict__ dyn,
                 const float* __restrict__ obs)
{
    const int tid = threadIdx.x;
    const int row = blockIdx.x * 2 + (tid >> 7);   // 2 rows per block
    const int seg = tid & 127;

    float o[2 * L];
    const float4* op = (const float4*)(obs + (size_t)row * (TT * 2) + seg * (2 * L));
#pragma unroll
    for (int i = 0; i < 4; i++) {
        float4 v = op[i];
        o[4 * i + 0] = v.x; o[4 * i + 1] = v.y;
        o[4 * i + 2] = v.z; o[4 * i + 3] = v.w;
    }
    int yb[L];
    const int4* cp = (const int4*)(corr + (size_t)row * TT + seg * L);
#pragma unroll
    for (int i = 0; i < 2; i++) {
        int4 v = cp[i];
        yb[4 * i + 0] = v.x; yb[4 * i + 1] = v.y;
        yb[4 * i + 2] = v.z; yb[4 * i + 3] = v.w;
    }

    float t00, t10, t01, t11;
    trans_from_dyn(dyn, row, t00, t10, t01, t11);

    float A00 = 1.f, A01 = 0.f, A10 = 0.f, A11 = 1.f;
#pragma unroll
    for (int j = 0; j < L; j++) {
        float e0 = __expf(o[2 * j]), e1 = __expf(o[2 * j + 1]);
        float r0 = frcp(1.f + e0);
        float r1 = frcp(1.f + e1);
        float py0 = yb[j] ? e0 * r0 : r0;
        float py1 = yb[j] ? r1 : e1 * r1;

        float m00 = t00 * py0, m01 = t01 * py1;
        float m10 = t10 * py0, m11 = t11 * py1;
        float n00 = m00 * A00 + m01 * A10;
        float n01 = m00 * A01 + m01 * A11;
        float n10 = m10 * A00 + m11 * A10;
        float n11 = m10 * A01 + m11 * A11;
        A00 = n00; A01 = n01; A10 = n10; A11 = n11;
    }
    g_P4[row * SEG + seg] = make_float4(A00, A01, A10, A11);   // coalesced contiguous
}

// ---------------- K2: boundary scan over segments (alpha & beta interleaved) ----------------
__global__ __launch_bounds__(64)
void k2_scan(const float* __restrict__ dyn)
{
    const int row = blockIdx.x * 64 + threadIdx.x;

    float d2 = dyn[row * 3 + 2];
    float ed2 = __expf(d2);
    float ri2 = frcp(1.f + ed2);
    float a0 = ri2, a1 = ed2 * ri2;
    int Ea = 0;
    float b0 = 1.f, b1 = 1.f;

#pragma unroll 8
    for (int k = 0; k < SEG; k++) {
        float s  = a0 + a1;
        float rs = frcp(s);
        float C  = (float)Ea * LN2F + __logf(s);
        g_ab[k * BN + row] = make_float4(a0 * rs, a1 * rs, C, 0.f);

        float4 P = g_P4[row * SEG + k];
        float na0 = P.x * a0 + P.y * a1;
        float na1 = P.z * a0 + P.w * a1;
        float ss = na0 + na1;
        int eb = (__float_as_int(ss) >> 23) & 0xFF;
        float sca = __int_as_float((254 - eb) << 23);
        a0 = na0 * sca; a1 = na1 * sca;
        Ea += eb - 127;

        int kb = SEG - 1 - k;
        g_bb[kb * BN + row] = make_float2(b0, b1);
        if (kb > 0) {
            float4 Pb = g_P4[row * SEG + kb];
            float nb0 = Pb.x * b0 + Pb.z * b1;   // P^T * b
            float nb1 = Pb.y * b0 + Pb.w * b1;
            float sb = nb0 + nb1;
            int ebb = (__float_as_int(sb) >> 23) & 0xFF;
            float scb = __int_as_float((254 - ebb) << 23);
            b0 = nb0 * scb; b1 = nb1 * scb;
        }
    }
}

// ---------------- K3: per-segment outputs (fwd-first, lean registers, no smem) ----------------
__global__ __launch_bounds__(128, 4)
void k3_outputs(const int* __restrict__ corr,
                const float* __restrict__ dyn,
                const float* __restrict__ obs,
                float* __restrict__ out)
{
    const int row = blockIdx.x;
    const int seg = threadIdx.x;

    float o[2 * L];
    const float4* op = (const float4*)(obs + (size_t)row * (TT * 2) + seg * (2 * L));
#pragma unroll
    for (int i = 0; i < 4; i++) {
        float4 v = op[i];
        o[4 * i + 0] = v.x; o[4 * i + 1] = v.y;
        o[4 * i + 2] = v.z; o[4 * i + 3] = v.w;
    }
    unsigned ymask = 0;
    const int4* cp = (const int4*)(corr + (size_t)row * TT + seg * L);
#pragma unroll
    for (int i = 0; i < 2; i++) {
        int4 v = cp[i];
        ymask |= (unsigned)(v.x & 1) << (4 * i + 0);
        ymask |= (unsigned)(v.y & 1) << (4 * i + 1);
        ymask |= (unsigned)(v.z & 1) << (4 * i + 2);
        ymask |= (unsigned)(v.w & 1) << (4 * i + 3);
    }

    float t00, t10, t01, t11;
    trans_from_dyn(dyn, row, t00, t10, t01, t11);

    const int gi = seg * BN + row;        // L2-hot (written by K2 just before)
    float4 ab = g_ab[gi];
    float a0 = ab.x, a1 = ab.y, C = ab.z;

    float4* predP = (float4*)(out + (size_t)row * (TT * 2) + seg * (2 * L));
    float4* postP = (float4*)(out + (size_t)BN * TT * 2 + (size_t)row * (TT * 2) + seg * (2 * L));
    float4* smP   = (float4*)(out + (size_t)2 * BN * TT * 2 + (size_t)row * (TT * 2) + seg * (2 * L));

    // ---- forward sub-walk: pred + post + f0; o[] replaced in place by emissions ----
    float f0s[L];
    float pr0 = 0.f, pr1 = 0.f, po0 = 0.f, po1 = 0.f;
#pragma unroll
    for (int j = 0; j < L; j++) {
        int y = (ymask >> j) & 1;
        float e0 = __expf(o[2 * j]), e1 = __expf(o[2 * j + 1]);
        float r0 = frcp(1.f + e0);
        float r1 = frcp(1.f + e1);
        float py0 = y ? e0 * r0 : r0;
        float py1 = y ? r1 : e1 * r1;
        o[2 * j]     = py0;              // reuse registers: logits -> emissions
        o[2 * j + 1] = py1;

        float jj0 = a0 * py0;
        float jj1 = a1 * py1;
        float js  = jj0 + jj1;           // predictive prob of observed symbol
        float ljs = __logf(js);
        float lns = __logf(1.f - js);    // predictive probs sum to 1 (a normalized)
        float lp0 = y ? lns : ljs;
        float lp1 = y ? ljs : lns;
        float post0 = __logf(jj0) + C;
        float post1 = __logf(jj1) + C;

        float f  = jj0 * frcp(js);
        f0s[j] = f;
        float fc = 1.f - f;
        a0 = t00 * f + t01 * fc;         // stays normalized (T columns sum to 1)
        a1 = t10 * f + t11 * fc;
        C += ljs;

        if ((j & 1) == 0) {
            pr0 = lp0; pr1 = lp1; po0 = post0; po1 = post1;
        } else {
            predP[j >> 1] = make_float4(pr0, pr1, lp0, lp1);
            postP[j >> 1] = make_float4(po0, po1, post0, post1);
        }
    }

    // ---- backward sub-walk: smoothed (descending; store pairs) ----
    float2 bb = g_bb[gi];
    float b0 = bb.x, b1 = bb.y;
    float sh0 = 0.f, sh1 = 0.f;
#pragma unroll
    for (int j = L - 1; j >= 0; j--) {
        float f  = f0s[j];
        float fc = 1.f - f;
        float g0 = f  * b0;
        float g1 = fc * b1;
        float rg = frcp(g0 + g1);
        float s0 = __logf(g0 * rg);
        float s1 = __logf(g1 * rg);

        if (j & 1) {
            sh0 = s0; sh1 = s1;
        } else {
            smP[j >> 1] = make_float4(s0, s1, sh0, sh1);
        }

        // beta update to t-1 (no in-segment rescale needed: >= ~1e-24)
        float u0 = o[2 * j]     * b0;
        float u1 = o[2 * j + 1] * b1;
        b0 = t00 * u0 + t10 * u1;
        b1 = t01 * u0 + t11 * u1;
    }
}

extern "C" void kernel_launch(void* const* d_in, const int* in_sizes, int n_in,
                              void* d_out, int out_size)
{
    const int*   corr = (const int*)d_in[0];
    const float* dyn  = (const float*)d_in[1];
    const float* obs  = (const float*)d_in[2];
    float* out = (float*)d_out;

    k1_products<<<BN / 2, 256>>>(corr, dyn, obs);
    k2_scan<<<BN / 64, 64>>>(dyn);
    k3_outputs<<<BN, 128>>>(corr, dyn, obs, out);
}